// round 5
// baseline (speedup 1.0000x reference)
#include <cuda_runtime.h>

#define NROWS 1024
#define MROWS 1024
#define DIM   512
#define DHALF 256

// GEMM partials: [z*2+kh] : z=0 -> hx, z=1 -> hy ; kh = k-half
__device__ float g_hp[4 * NROWS * DIM];
// pairwise partial sums, one buffer per d-half
__device__ float g_part[2 * NROWS * MROWS];

typedef unsigned long long u64;

#define ADD2(d, a, b) \
    asm("add.rn.f32x2 %0, %1, %2;" : "=l"(d) : "l"(a), "l"(b))
#define FMA2(d, a, b, c) \
    asm("fma.rn.f32x2 %0, %1, %2, %3;" : "=l"(d) : "l"(a), "l"(b), "l"(c))

__device__ __forceinline__ u64 relu2(u64 s) {
    unsigned int lo, hi;
    asm("mov.b64 {%0,%1}, %2;" : "=r"(lo), "=r"(hi) : "l"(s));
    float f0 = fmaxf(__uint_as_float(lo), 0.0f);
    float f1 = fmaxf(__uint_as_float(hi), 0.0f);
    u64 r;
    asm("mov.b64 %0, {%1,%2};"
        : "=l"(r) : "r"(__float_as_uint(f0)), "r"(__float_as_uint(f1)));
    return r;
}

__device__ __forceinline__ float hsum2(u64 s) {
    unsigned int lo, hi;
    asm("mov.b64 {%0,%1}, %2;" : "=r"(lo), "=r"(hi) : "l"(s));
    return __uint_as_float(lo) + __uint_as_float(hi);
}

// -------------------------------------------------------------------------
// GEMM v3: C[m][n] = sum_k A[m][k]*W[k][n], split-k2.
// A is read straight from global (L1 catches the 16x intra-block reuse;
// a-addresses are k-contiguous -> natural u64 k-pairs, zero crossbar cost).
// Only B goes through smem, transposed to Bs[n][k], stride 34
// (conflict-free STS.32 producer and LDS.64 consumer), double-buffered.
// grid (8 n-tiles, 16 m-tiles, 4 = {z}x{kh}), 64x64 tile, 4x4/thread.
// -------------------------------------------------------------------------
__global__ void __launch_bounds__(256) gemm_dual(const float* __restrict__ x,
                                                 const float* __restrict__ y,
                                                 const float* __restrict__ W1) {
    const int zz = blockIdx.z;        // 0..3
    const int z  = zz >> 1;           // which GEMM
    const int kh = zz & 1;            // which k-half
    const float* __restrict__ A = (z == 0) ? x : y;
    const float* __restrict__ W = W1 + z * DIM * DIM;
    float* __restrict__ C = g_hp + zz * (NROWS * DIM);

    __shared__ float Bs[2][64][34];

    const int tid = threadIdx.x;
    const int tn = tid & 15;
    const int tm = tid >> 4;
    const int m0 = blockIdx.y * 64;
    const int n0 = blockIdx.x * 64;
    const int kb = kh * 256;

    // B loader map: warp-constant column group, kr spans 0..31 within warp
    const int kr = tid & 31;
    const int c4 = tid >> 5;          // 0..7 (and +8 for second chunk)

    u64 acc[4][4];
#pragma unroll
    for (int i = 0; i < 4; i++)
#pragma unroll
        for (int j = 0; j < 4; j++) acc[i][j] = 0ULL;

    // prefetch + store first B tile
    float4 w0 = *(const float4*)&W[(kb + kr) * DIM + n0 + c4 * 4];
    float4 w1 = *(const float4*)&W[(kb + kr) * DIM + n0 + (c4 + 8) * 4];
    Bs[0][c4 * 4 + 0][kr] = w0.x;
    Bs[0][c4 * 4 + 1][kr] = w0.y;
    Bs[0][c4 * 4 + 2][kr] = w0.z;
    Bs[0][c4 * 4 + 3][kr] = w0.w;
    Bs[0][(c4 + 8) * 4 + 0][kr] = w1.x;
    Bs[0][(c4 + 8) * 4 + 1][kr] = w1.y;
    Bs[0][(c4 + 8) * 4 + 2][kr] = w1.z;
    Bs[0][(c4 + 8) * 4 + 3][kr] = w1.w;
    __syncthreads();

    const float* Ar0 = A + (m0 + tm * 4 + 0) * DIM + kb;
    const float* Ar1 = A + (m0 + tm * 4 + 1) * DIM + kb;
    const float* Ar2 = A + (m0 + tm * 4 + 2) * DIM + kb;
    const float* Ar3 = A + (m0 + tm * 4 + 3) * DIM + kb;

#pragma unroll
    for (int it = 0; it < 8; it++) {
        const int buf = it & 1;
        const int k0 = it * 32;

        if (it < 7) {
            const int kn = kb + (it + 1) * 32;
            w0 = *(const float4*)&W[(kn + kr) * DIM + n0 + c4 * 4];
            w1 = *(const float4*)&W[(kn + kr) * DIM + n0 + (c4 + 8) * 4];
        }

#pragma unroll
        for (int kc = 0; kc < 32; kc += 4) {
            ulonglong2 av0 = *(const ulonglong2*)&Ar0[k0 + kc];
            ulonglong2 av1 = *(const ulonglong2*)&Ar1[k0 + kc];
            ulonglong2 av2 = *(const ulonglong2*)&Ar2[k0 + kc];
            ulonglong2 av3 = *(const ulonglong2*)&Ar3[k0 + kc];
            u64 b0[4], b1[4];
#pragma unroll
            for (int j = 0; j < 4; j++) {
                b0[j] = *(const u64*)&Bs[buf][tn + 16 * j][kc];
                b1[j] = *(const u64*)&Bs[buf][tn + 16 * j][kc + 2];
            }
#pragma unroll
            for (int j = 0; j < 4; j++) {
                FMA2(acc[0][j], av0.x, b0[j], acc[0][j]);
                FMA2(acc[1][j], av1.x, b0[j], acc[1][j]);
                FMA2(acc[2][j], av2.x, b0[j], acc[2][j]);
                FMA2(acc[3][j], av3.x, b0[j], acc[3][j]);
                FMA2(acc[0][j], av0.y, b1[j], acc[0][j]);
                FMA2(acc[1][j], av1.y, b1[j], acc[1][j]);
                FMA2(acc[2][j], av2.y, b1[j], acc[2][j]);
                FMA2(acc[3][j], av3.y, b1[j], acc[3][j]);
            }
        }

        if (it < 7) {
            const int nb = buf ^ 1;
            Bs[nb][c4 * 4 + 0][kr] = w0.x;
            Bs[nb][c4 * 4 + 1][kr] = w0.y;
            Bs[nb][c4 * 4 + 2][kr] = w0.z;
            Bs[nb][c4 * 4 + 3][kr] = w0.w;
            Bs[nb][(c4 + 8) * 4 + 0][kr] = w1.x;
            Bs[nb][(c4 + 8) * 4 + 1][kr] = w1.y;
            Bs[nb][(c4 + 8) * 4 + 2][kr] = w1.z;
            Bs[nb][(c4 + 8) * 4 + 3][kr] = w1.w;
        }
        __syncthreads();
    }

#pragma unroll
    for (int i = 0; i < 4; i++)
#pragma unroll
        for (int j = 0; j < 4; j++)
            C[(m0 + tm * 4 + i) * DIM + n0 + tn + 16 * j] = hsum2(acc[i][j]);
}

// -------------------------------------------------------------------------
// Pairwise: part[z][i][j] = sum_{d in half z} relu(hx[i][d]+hy[j][d])*w2[d]
// hx/hy materialize here by summing the two GEMM k-half partials during
// the tile load. Strided row mapping (conflict-free), 3 blocks/SM.
// -------------------------------------------------------------------------
__global__ void __launch_bounds__(256, 3) pairwise_kernel(const float* __restrict__ w2) {
    __shared__ float xs[64][68];
    __shared__ float ys[64][68];
    __shared__ float w2s[64];

    const int tid = threadIdx.x;
    const int tx = tid & 15;
    const int ty = tid >> 4;
    const int i0 = blockIdx.y * 64;
    const int j0 = blockIdx.x * 64;
    const int z  = blockIdx.z;
    const int dbase = z * DHALF;

    const float* __restrict__ pxa = g_hp + 0 * (NROWS * DIM);
    const float* __restrict__ pxb = g_hp + 1 * (NROWS * DIM);
    const float* __restrict__ pya = g_hp + 2 * (NROWS * DIM);
    const float* __restrict__ pyb = g_hp + 3 * (NROWS * DIM);

    u64 acc[4][4];
#pragma unroll
    for (int i = 0; i < 4; i++)
#pragma unroll
        for (int j = 0; j < 4; j++) acc[i][j] = 0ULL;

    for (int d0 = 0; d0 < DHALF; d0 += 64) {
        const int dg = dbase + d0;
#pragma unroll
        for (int it = 0; it < 4; it++) {
            int f = tid + it * 256;
            int r = f >> 4;
            int c = f & 15;
            {
                float4 u = *(const float4*)&pxa[(i0 + r) * DIM + dg + c * 4];
                float4 v = *(const float4*)&pxb[(i0 + r) * DIM + dg + c * 4];
                float4 s = make_float4(u.x + v.x, u.y + v.y, u.z + v.z, u.w + v.w);
                *(float4*)&xs[r][c * 4] = s;
            }
            {
                float4 u = *(const float4*)&pya[(j0 + r) * DIM + dg + c * 4];
                float4 v = *(const float4*)&pyb[(j0 + r) * DIM + dg + c * 4];
                float4 s = make_float4(u.x + v.x, u.y + v.y, u.z + v.z, u.w + v.w);
                *(float4*)&ys[r][c * 4] = s;
            }
        }
        if (tid < 16)
            *(float4*)&w2s[tid * 4] = *(const float4*)&w2[dg + tid * 4];
        __syncthreads();

#pragma unroll 2
        for (int dd = 0; dd < 64; dd += 4) {
            u64 a[4][2], b[4][2];
#pragma unroll
            for (int ti = 0; ti < 4; ti++) {
                ulonglong2 av = *(const ulonglong2*)&xs[ty + 16 * ti][dd];
                a[ti][0] = av.x;
                a[ti][1] = av.y;
            }
#pragma unroll
            for (int tj = 0; tj < 4; tj++) {
                ulonglong2 bv = *(const ulonglong2*)&ys[tx + 16 * tj][dd];
                b[tj][0] = bv.x;
                b[tj][1] = bv.y;
            }
            ulonglong2 wv = *(const ulonglong2*)&w2s[dd];
            u64 w[2];
            w[0] = wv.x;
            w[1] = wv.y;
#pragma unroll
            for (int ti = 0; ti < 4; ti++)
#pragma unroll
                for (int tj = 0; tj < 4; tj++) {
#pragma unroll
                    for (int p = 0; p < 2; p++) {
                        u64 s;
                        ADD2(s, a[ti][p], b[tj][p]);
                        s = relu2(s);
                        FMA2(acc[ti][tj], s, w[p], acc[ti][tj]);
                    }
                }
        }
        __syncthreads();
    }

    float* __restrict__ part = g_part + z * (NROWS * MROWS);
#pragma unroll
    for (int ti = 0; ti < 4; ti++)
#pragma unroll
        for (int tj = 0; tj < 4; tj++)
            part[(i0 + ty + 16 * ti) * MROWS + j0 + tx + 16 * tj] =
                hsum2(acc[ti][tj]);
}

__global__ void __launch_bounds__(256) reduce_add(float* __restrict__ out) {
    int idx = (blockIdx.x * 256 + threadIdx.x) * 4;
    float4 a = *(const float4*)&g_part[idx];
    float4 b = *(const float4*)&g_part[NROWS * MROWS + idx];
    float4 o;
    o.x = a.x + b.x;
    o.y = a.y + b.y;
    o.z = a.z + b.z;
    o.w = a.w + b.w;
    *(float4*)&out[idx] = o;
}

extern "C" void kernel_launch(void* const* d_in, const int* in_sizes, int n_in,
                              void* d_out, int out_size) {
    const float* x  = (const float*)d_in[0];
    const float* y  = (const float*)d_in[1];
    const float* W1 = (const float*)d_in[2];
    const float* W2 = (const float*)d_in[3];
    float* out = (float*)d_out;

    dim3 ggrid(DIM / 64, NROWS / 64, 4);     // (8, 16, 4) = 512 blocks
    gemm_dual<<<ggrid, 256>>>(x, y, W1);

    dim3 pgrid(MROWS / 64, NROWS / 64, 2);   // (16, 16, 2)
    pairwise_kernel<<<pgrid, 256>>>(W2);

    reduce_add<<<(NROWS * MROWS) / 1024, 256>>>(out);
}

// round 6
// speedup vs baseline: 1.0448x; 1.0448x over previous
#include <cuda_runtime.h>

#define NROWS 1024
#define MROWS 1024
#define DIM   512
#define DHALF 256

// GEMM partials: zz = z*2+kh : z=0 -> hx, z=1 -> hy ; kh = k-half
__device__ float g_hp[4 * NROWS * DIM];
// pairwise partial sums, one buffer per d-half
__device__ float g_part[2 * NROWS * MROWS];

typedef unsigned long long u64;

#define ADD2(d, a, b) \
    asm("add.rn.f32x2 %0, %1, %2;" : "=l"(d) : "l"(a), "l"(b))
#define FMA2(d, a, b, c) \
    asm("fma.rn.f32x2 %0, %1, %2, %3;" : "=l"(d) : "l"(a), "l"(b), "l"(c))

__device__ __forceinline__ u64 relu2(u64 s) {
    unsigned int lo, hi;
    asm("mov.b64 {%0,%1}, %2;" : "=r"(lo), "=r"(hi) : "l"(s));
    float f0 = fmaxf(__uint_as_float(lo), 0.0f);
    float f1 = fmaxf(__uint_as_float(hi), 0.0f);
    u64 r;
    asm("mov.b64 %0, {%1,%2};"
        : "=l"(r) : "r"(__float_as_uint(f0)), "r"(__float_as_uint(f1)));
    return r;
}

__device__ __forceinline__ float hsum2(u64 s) {
    unsigned int lo, hi;
    asm("mov.b64 {%0,%1}, %2;" : "=r"(lo), "=r"(hi) : "l"(s));
    return __uint_as_float(lo) + __uint_as_float(hi);
}

// -------------------------------------------------------------------------
// GEMM (R4 smem design + split-k2 + 3 blocks/SM).
// C[m][n] = sum_{k in half kh} A[m][k]*W[k][n].
// As stride 36 (a-loads are 2-addr broadcasts), Bs stride 34 (conflict-free
// STS.32 producer / LDS.64 consumer), double-buffered, 1 sync/iter.
// grid (8,16,4): z = GEMM id, kh = k-half -> 512 blocks.
// -------------------------------------------------------------------------
__global__ void __launch_bounds__(256, 3) gemm_dual(const float* __restrict__ x,
                                                    const float* __restrict__ y,
                                                    const float* __restrict__ W1) {
    const int zz = blockIdx.z;
    const int z  = zz >> 1;
    const int kh = zz & 1;
    const float* __restrict__ A = (z == 0) ? x : y;
    const float* __restrict__ W = W1 + z * DIM * DIM;
    float* __restrict__ C = g_hp + zz * (NROWS * DIM);

    __shared__ float As[2][64][36];
    __shared__ float Bs[2][64][34];

    const int tid = threadIdx.x;
    const int tn = tid & 15;
    const int tm = tid >> 4;
    const int m0 = blockIdx.y * 64;
    const int n0 = blockIdx.x * 64;
    const int kb = kh * 256;

    const int ar = tid >> 3;     // A row base (0..31), +32 for it=1
    const int ac = tid & 7;      // A col4
    const int wk = tid >> 4;     // W k-row base (0..15), +16 for it=1
    const int wc = tid & 15;     // W col4

    u64 acc[4][4];
#pragma unroll
    for (int i = 0; i < 4; i++)
#pragma unroll
        for (int j = 0; j < 4; j++) acc[i][j] = 0ULL;

    float4 aS[2], wS[2];
#pragma unroll
    for (int it = 0; it < 2; it++) {
        aS[it] = *(const float4*)&A[(m0 + ar + it * 32) * DIM + kb + ac * 4];
        wS[it] = *(const float4*)&W[(kb + wk + it * 16) * DIM + n0 + wc * 4];
    }
#pragma unroll
    for (int it = 0; it < 2; it++) {
        *(float4*)&As[0][ar + it * 32][ac * 4] = aS[it];
        Bs[0][wc * 4 + 0][wk + it * 16] = wS[it].x;
        Bs[0][wc * 4 + 1][wk + it * 16] = wS[it].y;
        Bs[0][wc * 4 + 2][wk + it * 16] = wS[it].z;
        Bs[0][wc * 4 + 3][wk + it * 16] = wS[it].w;
    }
    __syncthreads();

#pragma unroll 2
    for (int k0i = 0; k0i < 8; k0i++) {
        const int buf = k0i & 1;
        if (k0i < 7) {
            const int kng = kb + (k0i + 1) * 32;
#pragma unroll
            for (int it = 0; it < 2; it++) {
                aS[it] = *(const float4*)&A[(m0 + ar + it * 32) * DIM + kng + ac * 4];
                wS[it] = *(const float4*)&W[(kng + wk + it * 16) * DIM + n0 + wc * 4];
            }
        }

#pragma unroll
        for (int kk = 0; kk < 32; kk += 2) {
            u64 a2[4], b2[4];
#pragma unroll
            for (int i = 0; i < 4; i++)
                a2[i] = *(const u64*)&As[buf][tm * 4 + i][kk];
#pragma unroll
            for (int j = 0; j < 4; j++)
                b2[j] = *(const u64*)&Bs[buf][tn + 16 * j][kk];
#pragma unroll
            for (int i = 0; i < 4; i++)
#pragma unroll
                for (int j = 0; j < 4; j++)
                    FMA2(acc[i][j], a2[i], b2[j], acc[i][j]);
        }

        if (k0i < 7) {
            const int nb = buf ^ 1;
#pragma unroll
            for (int it = 0; it < 2; it++) {
                *(float4*)&As[nb][ar + it * 32][ac * 4] = aS[it];
                Bs[nb][wc * 4 + 0][wk + it * 16] = wS[it].x;
                Bs[nb][wc * 4 + 1][wk + it * 16] = wS[it].y;
                Bs[nb][wc * 4 + 2][wk + it * 16] = wS[it].z;
                Bs[nb][wc * 4 + 3][wk + it * 16] = wS[it].w;
            }
        }
        __syncthreads();
    }

#pragma unroll
    for (int i = 0; i < 4; i++)
#pragma unroll
        for (int j = 0; j < 4; j++)
            C[(m0 + tm * 4 + i) * DIM + n0 + tn + 16 * j] = hsum2(acc[i][j]);
}

// -------------------------------------------------------------------------
// Pairwise: part[z][i][j] = sum_{d in half z} relu(hx[i][d]+hy[j][d])*w2[d]
// hx/hy materialize from the 2 GEMM k-half partials during tile load.
// Tiles are stride-64 rows with XOR-8 swizzle on 16B chunks:
//   addr(r, chunk) = r*64 + ((chunk ^ (r&7)) << 2)
// -> b LDS.128 over 16 strided rows = 2 conflict-free phases (minimum).
// -------------------------------------------------------------------------
__global__ void __launch_bounds__(256, 3) pairwise_kernel(const float* __restrict__ w2) {
    __shared__ float xs[64 * 64];
    __shared__ float ys[64 * 64];
    __shared__ float w2s[64];

    const int tid = threadIdx.x;
    const int tx = tid & 15;
    const int ty = tid >> 4;
    const int txp = tx & 7;
    const int typ = ty & 7;
    const int i0 = blockIdx.y * 64;
    const int j0 = blockIdx.x * 64;
    const int z  = blockIdx.z;
    const int dbase = z * DHALF;

    const float* __restrict__ pxa = g_hp + 0 * (NROWS * DIM);
    const float* __restrict__ pxb = g_hp + 1 * (NROWS * DIM);
    const float* __restrict__ pya = g_hp + 2 * (NROWS * DIM);
    const float* __restrict__ pyb = g_hp + 3 * (NROWS * DIM);

    u64 acc[4][4];
#pragma unroll
    for (int i = 0; i < 4; i++)
#pragma unroll
        for (int j = 0; j < 4; j++) acc[i][j] = 0ULL;

    for (int d0 = 0; d0 < DHALF; d0 += 64) {
        const int dg = dbase + d0;
#pragma unroll
        for (int it = 0; it < 4; it++) {
            int f = tid + it * 256;
            int r = f >> 4;          // 0..63
            int c = f & 15;          // chunk 0..15
            int sw = r * 64 + (((c ^ (r & 7))) << 2);
            {
                float4 u = *(const float4*)&pxa[(i0 + r) * DIM + dg + c * 4];
                float4 v = *(const float4*)&pxb[(i0 + r) * DIM + dg + c * 4];
                *(float4*)&xs[sw] =
                    make_float4(u.x + v.x, u.y + v.y, u.z + v.z, u.w + v.w);
            }
            {
                float4 u = *(const float4*)&pya[(j0 + r) * DIM + dg + c * 4];
                float4 v = *(const float4*)&pyb[(j0 + r) * DIM + dg + c * 4];
                *(float4*)&ys[sw] =
                    make_float4(u.x + v.x, u.y + v.y, u.z + v.z, u.w + v.w);
            }
        }
        if (tid < 16)
            *(float4*)&w2s[tid * 4] = *(const float4*)&w2[dg + tid * 4];
        __syncthreads();

#pragma unroll 2
        for (int dd = 0; dd < 64; dd += 4) {
            const int q = dd >> 2;
            const int qa = (q ^ typ) << 2;
            const int qb = (q ^ txp) << 2;
            u64 a[4][2], b[4][2];
#pragma unroll
            for (int ti = 0; ti < 4; ti++) {
                ulonglong2 av = *(const ulonglong2*)&xs[(ty + 16 * ti) * 64 + qa];
                a[ti][0] = av.x;
                a[ti][1] = av.y;
            }
#pragma unroll
            for (int tj = 0; tj < 4; tj++) {
                ulonglong2 bv = *(const ulonglong2*)&ys[(tx + 16 * tj) * 64 + qb];
                b[tj][0] = bv.x;
                b[tj][1] = bv.y;
            }
            ulonglong2 wv = *(const ulonglong2*)&w2s[dd];
            u64 w[2];
            w[0] = wv.x;
            w[1] = wv.y;
#pragma unroll
            for (int ti = 0; ti < 4; ti++)
#pragma unroll
                for (int tj = 0; tj < 4; tj++) {
#pragma unroll
                    for (int p = 0; p < 2; p++) {
                        u64 s;
                        ADD2(s, a[ti][p], b[tj][p]);
                        s = relu2(s);
                        FMA2(acc[ti][tj], s, w[p], acc[ti][tj]);
                    }
                }
        }
        __syncthreads();
    }

    float* __restrict__ part = g_part + z * (NROWS * MROWS);
#pragma unroll
    for (int ti = 0; ti < 4; ti++)
#pragma unroll
        for (int tj = 0; tj < 4; tj++)
            part[(i0 + ty + 16 * ti) * MROWS + j0 + tx + 16 * tj] =
                hsum2(acc[ti][tj]);
}

__global__ void __launch_bounds__(256) reduce_add(float* __restrict__ out) {
    int idx = (blockIdx.x * 256 + threadIdx.x) * 4;
    float4 a = *(const float4*)&g_part[idx];
    float4 b = *(const float4*)&g_part[NROWS * MROWS + idx];
    float4 o;
    o.x = a.x + b.x;
    o.y = a.y + b.y;
    o.z = a.z + b.z;
    o.w = a.w + b.w;
    *(float4*)&out[idx] = o;
}

extern "C" void kernel_launch(void* const* d_in, const int* in_sizes, int n_in,
                              void* d_out, int out_size) {
    const float* x  = (const float*)d_in[0];
    const float* y  = (const float*)d_in[1];
    const float* W1 = (const float*)d_in[2];
    const float* W2 = (const float*)d_in[3];
    float* out = (float*)d_out;

    dim3 ggrid(DIM / 64, NROWS / 64, 4);     // 512 blocks
    gemm_dual<<<ggrid, 256>>>(x, y, W1);

    dim3 pgrid(MROWS / 64, NROWS / 64, 2);   // 512 blocks
    pairwise_kernel<<<pgrid, 256>>>(W2);

    reduce_add<<<(NROWS * MROWS) / 1024, 256>>>(out);
}

// round 7
// speedup vs baseline: 1.1102x; 1.0626x over previous
#include <cuda_runtime.h>

#define NROWS 1024
#define MROWS 1024
#define DIM   512
#define DHALF 256

__device__ float g_hx[NROWS * DIM];
__device__ float g_hy[MROWS * DIM];
__device__ float g_part[2 * NROWS * MROWS];

typedef unsigned long long u64;

#define ADD2(d, a, b) \
    asm("add.rn.f32x2 %0, %1, %2;" : "=l"(d) : "l"(a), "l"(b))
#define FMA2(d, a, b, c) \
    asm("fma.rn.f32x2 %0, %1, %2, %3;" : "=l"(d) : "l"(a), "l"(b), "l"(c))

__device__ __forceinline__ u64 relu2(u64 s) {
    unsigned int lo, hi;
    asm("mov.b64 {%0,%1}, %2;" : "=r"(lo), "=r"(hi) : "l"(s));
    float f0 = fmaxf(__uint_as_float(lo), 0.0f);
    float f1 = fmaxf(__uint_as_float(hi), 0.0f);
    u64 r;
    asm("mov.b64 %0, {%1,%2};"
        : "=l"(r) : "r"(__float_as_uint(f0)), "r"(__float_as_uint(f1)));
    return r;
}

__device__ __forceinline__ float hsum2(u64 s) {
    unsigned int lo, hi;
    asm("mov.b64 {%0,%1}, %2;" : "=r"(lo), "=r"(hi) : "l"(s));
    return __uint_as_float(lo) + __uint_as_float(hi);
}

// -------------------------------------------------------------------------
// GEMM: C[m][n] = sum_k A[m][k]*W[k][n]. No split-k (R4 baseline) +
// explicit register fragment double-buffering in the kk loop so LDS
// latency overlaps FMA work. As stride 36 (broadcast a-loads),
// Bs stride 34 (conflict-free STS.32 / LDS.64), smem double-buffered.
// grid (8,16,2), 64x64 tile, 4x4/thread, launch_bounds(256,2).
// -------------------------------------------------------------------------
__global__ void __launch_bounds__(256, 2) gemm_dual(const float* __restrict__ x,
                                                    const float* __restrict__ y,
                                                    const float* __restrict__ W1) {
    const int z = blockIdx.z;
    const float* __restrict__ A = (z == 0) ? x : y;
    const float* __restrict__ W = W1 + z * DIM * DIM;
    float* __restrict__ C = (z == 0) ? g_hx : g_hy;

    __shared__ float As[2][64][36];
    __shared__ float Bs[2][64][34];

    const int tid = threadIdx.x;
    const int tn = tid & 15;
    const int tm = tid >> 4;
    const int m0 = blockIdx.y * 64;
    const int n0 = blockIdx.x * 64;

    const int ar = tid >> 3;     // A row base (0..31), +32 for it=1
    const int ac = tid & 7;      // A col4
    const int wk = tid >> 4;     // W k-row base (0..15), +16 for it=1
    const int wc = tid & 15;     // W col4

    u64 acc[4][4];
#pragma unroll
    for (int i = 0; i < 4; i++)
#pragma unroll
        for (int j = 0; j < 4; j++) acc[i][j] = 0ULL;

    float4 aS[2], wS[2];
#pragma unroll
    for (int it = 0; it < 2; it++) {
        aS[it] = *(const float4*)&A[(m0 + ar + it * 32) * DIM + ac * 4];
        wS[it] = *(const float4*)&W[(wk + it * 16) * DIM + n0 + wc * 4];
    }
#pragma unroll
    for (int it = 0; it < 2; it++) {
        *(float4*)&As[0][ar + it * 32][ac * 4] = aS[it];
        Bs[0][wc * 4 + 0][wk + it * 16] = wS[it].x;
        Bs[0][wc * 4 + 1][wk + it * 16] = wS[it].y;
        Bs[0][wc * 4 + 2][wk + it * 16] = wS[it].z;
        Bs[0][wc * 4 + 3][wk + it * 16] = wS[it].w;
    }
    __syncthreads();

    // register fragment double buffer
    u64 a2[2][4], b2[2][4];
#pragma unroll
    for (int i = 0; i < 4; i++) a2[0][i] = *(const u64*)&As[0][tm * 4 + i][0];
#pragma unroll
    for (int j = 0; j < 4; j++) b2[0][j] = *(const u64*)&Bs[0][tn + 16 * j][0];

    for (int k0i = 0; k0i < 16; k0i++) {
        const int buf = k0i & 1;
        if (k0i < 15) {
            const int kng = (k0i + 1) * 32;
#pragma unroll
            for (int it = 0; it < 2; it++) {
                aS[it] = *(const float4*)&A[(m0 + ar + it * 32) * DIM + kng + ac * 4];
                wS[it] = *(const float4*)&W[(kng + wk + it * 16) * DIM + n0 + wc * 4];
            }
        }

#pragma unroll
        for (int kk = 0; kk < 32; kk += 2) {
            const int cur = (kk >> 1) & 1;
            const int nxt = cur ^ 1;
            if (kk < 30) {
#pragma unroll
                for (int i = 0; i < 4; i++)
                    a2[nxt][i] = *(const u64*)&As[buf][tm * 4 + i][kk + 2];
#pragma unroll
                for (int j = 0; j < 4; j++)
                    b2[nxt][j] = *(const u64*)&Bs[buf][tn + 16 * j][kk + 2];
            }
#pragma unroll
            for (int i = 0; i < 4; i++)
#pragma unroll
                for (int j = 0; j < 4; j++)
                    FMA2(acc[i][j], a2[cur][i], b2[cur][j], acc[i][j]);
        }

        if (k0i < 15) {
            const int nb = buf ^ 1;
#pragma unroll
            for (int it = 0; it < 2; it++) {
                *(float4*)&As[nb][ar + it * 32][ac * 4] = aS[it];
                Bs[nb][wc * 4 + 0][wk + it * 16] = wS[it].x;
                Bs[nb][wc * 4 + 1][wk + it * 16] = wS[it].y;
                Bs[nb][wc * 4 + 2][wk + it * 16] = wS[it].z;
                Bs[nb][wc * 4 + 3][wk + it * 16] = wS[it].w;
            }
        }
        __syncthreads();
        if (k0i < 15) {
            const int nb = buf ^ 1;
#pragma unroll
            for (int i = 0; i < 4; i++)
                a2[0][i] = *(const u64*)&As[nb][tm * 4 + i][0];
#pragma unroll
            for (int j = 0; j < 4; j++)
                b2[0][j] = *(const u64*)&Bs[nb][tn + 16 * j][0];
        }
    }

#pragma unroll
    for (int i = 0; i < 4; i++)
#pragma unroll
        for (int j = 0; j < 4; j++)
            C[(m0 + tm * 4 + i) * DIM + n0 + tn + 16 * j] = hsum2(acc[i][j]);
}

// -------------------------------------------------------------------------
// Pairwise (R4 form): part[z][i][j] = sum_{d in half z} relu(hx+hy)*w2
// 64x64 tile, 4x4/thread strided rows, stride-68 padded smem, 3 blocks/SM.
// -------------------------------------------------------------------------
__global__ void __launch_bounds__(256, 3) pairwise_kernel(const float* __restrict__ w2) {
    __shared__ float xs[64][68];
    __shared__ float ys[64][68];
    __shared__ float w2s[64];

    const int tid = threadIdx.x;
    const int tx = tid & 15;
    const int ty = tid >> 4;
    const int i0 = blockIdx.y * 64;
    const int j0 = blockIdx.x * 64;
    const int z  = blockIdx.z;
    const int dbase = z * DHALF;

    u64 acc[4][4];
#pragma unroll
    for (int i = 0; i < 4; i++)
#pragma unroll
        for (int j = 0; j < 4; j++) acc[i][j] = 0ULL;

    for (int d0 = 0; d0 < DHALF; d0 += 64) {
        const int dg = dbase + d0;
#pragma unroll
        for (int it = 0; it < 4; it++) {
            int f = tid + it * 256;
            int r = f >> 4;
            int c = f & 15;
            *(float4*)&xs[r][c * 4] =
                *(const float4*)&g_hx[(i0 + r) * DIM + dg + c * 4];
            *(float4*)&ys[r][c * 4] =
                *(const float4*)&g_hy[(j0 + r) * DIM + dg + c * 4];
        }
        if (tid < 16)
            *(float4*)&w2s[tid * 4] = *(const float4*)&w2[dg + tid * 4];
        __syncthreads();

#pragma unroll 2
        for (int dd = 0; dd < 64; dd += 4) {
            u64 a[4][2], b[4][2];
#pragma unroll
            for (int ti = 0; ti < 4; ti++) {
                ulonglong2 av = *(const ulonglong2*)&xs[ty + 16 * ti][dd];
                a[ti][0] = av.x;
                a[ti][1] = av.y;
            }
#pragma unroll
            for (int tj = 0; tj < 4; tj++) {
                ulonglong2 bv = *(const ulonglong2*)&ys[tx + 16 * tj][dd];
                b[tj][0] = bv.x;
                b[tj][1] = bv.y;
            }
            ulonglong2 wv = *(const ulonglong2*)&w2s[dd];
            u64 w[2];
            w[0] = wv.x;
            w[1] = wv.y;
#pragma unroll
            for (int ti = 0; ti < 4; ti++)
#pragma unroll
                for (int tj = 0; tj < 4; tj++) {
#pragma unroll
                    for (int p = 0; p < 2; p++) {
                        u64 s;
                        ADD2(s, a[ti][p], b[tj][p]);
                        s = relu2(s);
                        FMA2(acc[ti][tj], s, w[p], acc[ti][tj]);
                    }
                }
        }
        __syncthreads();
    }

    float* __restrict__ part = g_part + z * (NROWS * MROWS);
#pragma unroll
    for (int ti = 0; ti < 4; ti++)
#pragma unroll
        for (int tj = 0; tj < 4; tj++)
            part[(i0 + ty + 16 * ti) * MROWS + j0 + tx + 16 * tj] =
                hsum2(acc[ti][tj]);
}

__global__ void __launch_bounds__(256) reduce_add(float* __restrict__ out) {
    int idx = (blockIdx.x * 256 + threadIdx.x) * 4;
    float4 a = *(const float4*)&g_part[idx];
    float4 b = *(const float4*)&g_part[NROWS * MROWS + idx];
    float4 o;
    o.x = a.x + b.x;
    o.y = a.y + b.y;
    o.z = a.z + b.z;
    o.w = a.w + b.w;
    *(float4*)&out[idx] = o;
}

extern "C" void kernel_launch(void* const* d_in, const int* in_sizes, int n_in,
                              void* d_out, int out_size) {
    const float* x  = (const float*)d_in[0];
    const float* y  = (const float*)d_in[1];
    const float* W1 = (const float*)d_in[2];
    const float* W2 = (const float*)d_in[3];
    float* out = (float*)d_out;

    dim3 ggrid(DIM / 64, NROWS / 64, 2);     // 256 blocks
    gemm_dual<<<ggrid, 256>>>(x, y, W1);

    dim3 pgrid(MROWS / 64, NROWS / 64, 2);   // 512 blocks
    pairwise_kernel<<<pgrid, 256>>>(W2);

    reduce_add<<<(NROWS * MROWS) / 1024, 256>>>(out);
}